// round 16
// baseline (speedup 1.0000x reference)
#include <cuda_runtime.h>
#include <cuda_bf16.h>
#include <cuda_fp16.h>

// ---------------------------------------------------------------------------
// AtlasAttention, legacy mma.sync fp16 single-pass, fused MLP.
//   prep:  hs -> fp16 scratch; Wq^T coalesced 64x64 tile transpose
//   GEMM1: q = clip(hs@Wq) -> g_qs fp16; BN=64 tiles (832-block grid ->
//          2.81 waves, 81%-full tail vs 51% at BN=128). y==12: W1T/W2T/b1eff.
//   GEMM2: h = relu(P@W1eff + b1eff)   GEMM3: out = H@W2[:, :64] + b2
//   Exact folds: b1eff (const poly block), W2[:, :64] slice.
// ---------------------------------------------------------------------------

typedef unsigned int u32;

#define TOKENS 8192
#define HIDDEN 768
#define FLATR  98304
#define MEMH   512
#define KP     192
#define HD     64

__device__ __align__(16) __half g_hs_f[TOKENS * HIDDEN];
__device__ __align__(16) __half g_wqt[HIDDEN * HIDDEN];   // [n][k] fp16
__device__ __align__(16) __half g_w1t[MEMH * KP];         // [n=512][k=192]
__device__ __align__(16) __half g_w2t[HD * MEMH];         // [n=64][k=512]
__device__ __align__(16) __half g_qs[(size_t)TOKENS * HIDDEN];  // clipped q, fp16
__device__ float g_b1eff[MEMH];

// ---------------- helpers ----------------
__device__ __forceinline__ u32 smem_u32(const void* p) {
    u32 a; asm("{ .reg .u64 t; cvta.to.shared.u64 t, %1; cvt.u32.u64 %0, t; }"
               : "=r"(a) : "l"(p)); return a;
}
__device__ __forceinline__ u32 pack_h(__half a, __half b) {
    return (u32)__half_as_ushort(a) | ((u32)__half_as_ushort(b) << 16);
}
__device__ __forceinline__ void mma16816(float* c, const u32* a, const u32* b) {
    asm volatile(
        "mma.sync.aligned.m16n8k16.row.col.f32.f16.f16.f32 "
        "{%0,%1,%2,%3}, {%4,%5,%6,%7}, {%8,%9}, {%0,%1,%2,%3};"
        : "+f"(c[0]), "+f"(c[1]), "+f"(c[2]), "+f"(c[3])
        : "r"(a[0]), "r"(a[1]), "r"(a[2]), "r"(a[3]), "r"(b[0]), "r"(b[1]));
}
__device__ __forceinline__ void cpasync16(u32 dst, const void* src) {
    asm volatile("cp.async.cg.shared.global [%0], [%1], 16;" :: "r"(dst), "l"(src));
}

// ---------------- prep kernel: hs->fp16 + Wq^T only ----------------
#define NB_HS   1536
#define NB_WQT  144
#define NB_ALL  (NB_HS + NB_WQT)

__global__ void prep_all(const float* __restrict__ hs, const float* __restrict__ Wq) {
    const int b = blockIdx.x, tid = threadIdx.x;
    if (b < NB_HS) {
        #pragma unroll
        for (int j = 0; j < 4; j++) {
            int i4 = (b * 256 + tid) + j * (NB_HS * 256);
            float4 v = ((const float4*)hs)[i4];
            u32 f0 = pack_h(__float2half_rn(v.x), __float2half_rn(v.y));
            u32 f1 = pack_h(__float2half_rn(v.z), __float2half_rn(v.w));
            ((uint2*)g_hs_f)[i4] = make_uint2(f0, f1);
        }
    } else {
        __shared__ float ts[64][65];
        int t = b - NB_HS;
        int kb = (t / 12) * 64, nb = (t % 12) * 64;
        int tx = tid & 63, ty = tid >> 6;
        #pragma unroll
        for (int i = 0; i < 16; i++) {
            int row = ty + i * 4;
            ts[row][tx] = Wq[(size_t)(kb + row) * HIDDEN + nb + tx];
        }
        __syncthreads();
        #pragma unroll
        for (int i = 0; i < 16; i++) {
            int n = ty + i * 4;
            g_wqt[(size_t)(nb + n) * HIDDEN + kb + tx] = __float2half_rn(ts[tx][n]);
        }
    }
}

// ---------------- GEMM1 (BN=64) + embedded MLP-weight prep ------------------
// grid (64, 13): y<12 -> GEMM tile (128 x 64); y==12 -> prep items:
//   [0,96): W1T 32x32 tiles; [96,128): W2T 32x32 tiles; [128,130): b1eff
__global__ __launch_bounds__(256) void gemm1_kernel(const float* __restrict__ W1,
                                                    const float* __restrict__ W2,
                                                    const float* __restrict__ b1,
                                                    const float* __restrict__ coeffs) {
    constexpr int BM = 128, BN = 64, BK = 32, NT = 4;
    constexpr int SA = 20;
    constexpr int TILE_A = BM * SA, TILE_B = BN * SA;
    constexpr int STAGE = TILE_A + TILE_B;                  // 3840 u32
    constexpr int K = HIDDEN, NIT = K / BK;

    extern __shared__ u32 smem[];
    const int tid = threadIdx.x;

    if (blockIdx.y == 12) {
        float* ts = (float*)smem;                    // [32][33]
        const int tx = tid & 31, ty = tid >> 5;
        for (int item = blockIdx.x; item < 130; item += 64) {
            if (item < 96) {
                int kb = (item / 16) * 32, nb = (item % 16) * 32;
                #pragma unroll
                for (int i = 0; i < 4; i++) {
                    int kr = ty + i * 8;
                    ts[kr * 33 + tx] = W1[(size_t)(HD + kb + kr) * MEMH + nb + tx];
                }
                __syncthreads();
                #pragma unroll
                for (int i = 0; i < 4; i++) {
                    int n = ty + i * 8;
                    g_w1t[(size_t)(nb + n) * KP + kb + tx] = __float2half_rn(ts[tx * 33 + n]);
                }
                __syncthreads();
            } else if (item < 128) {
                int t = item - 96;
                int kb = (t / 2) * 32, nb = (t % 2) * 32;
                #pragma unroll
                for (int i = 0; i < 4; i++) {
                    int kr = ty + i * 8;
                    ts[kr * 33 + tx] = W2[(size_t)(kb + kr) * 256 + nb + tx];
                }
                __syncthreads();
                #pragma unroll
                for (int i = 0; i < 4; i++) {
                    int n = ty + i * 8;
                    g_w2t[(size_t)(nb + n) * MEMH + kb + tx] = __float2half_rn(ts[tx * 33 + n]);
                }
                __syncthreads();
            } else {
                int n = (item - 128) * 256 + tid;
                float s = 0.f;
                #pragma unroll 8
                for (int j = 0; j < HD; j++) s += W1[j * MEMH + n];
                g_b1eff[n] = b1[n] + coeffs[0] * s;
            }
        }
        return;
    }

    const u32 sbase = smem_u32(smem);
    const int wid = tid >> 5, lane = tid & 31;
    const int g = lane >> 2, tg = lane & 3;
    const int m0 = blockIdx.x * BM, n0 = blockIdx.y * BN;
    const int warpM = wid & 3, warpN = wid >> 2;            // warpN in {0,1}

    float acc[2][NT][4];
    #pragma unroll
    for (int mt = 0; mt < 2; mt++)
        #pragma unroll
        for (int nt = 0; nt < NT; nt++)
            #pragma unroll
            for (int j = 0; j < 4; j++) acc[mt][nt][j] = 0.f;

    auto load_stage = [&](int s, int k0) {
        const u32 stb = sbase + (u32)s * STAGE * 4;
        #pragma unroll
        for (int idx = 0; idx < 2; idx++) {
            int l = tid + idx * 256;
            int r = l >> 2, c = l & 3;
            cpasync16(stb + (u32)(r * SA) * 4 + c * 16,
                      g_hs_f + (size_t)(m0 + r) * K + k0 + c * 8);
        }
        {
            int r = tid >> 2, c = tid & 3;               // 64 rows * 4 chunks
            cpasync16(stb + (u32)(TILE_A + r * SA) * 4 + c * 16,
                      g_wqt + (size_t)(n0 + r) * K + k0 + c * 8);
        }
        asm volatile("cp.async.commit_group;");
    };

    load_stage(0, 0);
    for (int it = 0; it < NIT; it++) {
        if (it + 1 < NIT) {
            load_stage((it + 1) & 1, (it + 1) * BK);
            asm volatile("cp.async.wait_group %0;" :: "n"(1));
        } else {
            asm volatile("cp.async.wait_group %0;" :: "n"(0));
        }
        __syncthreads();
        const u32* S = smem + (it & 1) * STAGE;
        #pragma unroll
        for (int kt = 0; kt < 2; kt++) {
            u32 af[2][4];
            #pragma unroll
            for (int mt = 0; mt < 2; mt++) {
                int off = (warpM * 32 + mt * 16 + g) * SA + kt * 8 + tg;
                af[mt][0] = S[off];       af[mt][1] = S[off + 8 * SA];
                af[mt][2] = S[off + 4];   af[mt][3] = S[off + 8 * SA + 4];
            }
            u32 bv[NT][2];
            #pragma unroll
            for (int nt = 0; nt < NT; nt++) {
                int off = (warpN * 32 + nt * 8 + g) * SA + kt * 8 + tg;
                const u32* SB = S + TILE_A;
                bv[nt][0] = SB[off]; bv[nt][1] = SB[off + 4];
            }
            #pragma unroll
            for (int mt = 0; mt < 2; mt++)
                #pragma unroll
                for (int nt = 0; nt < NT; nt++) mma16816(acc[mt][nt], af[mt], bv[nt]);
        }
        __syncthreads();
    }

    #pragma unroll
    for (int mt = 0; mt < 2; mt++)
        #pragma unroll
        for (int nt = 0; nt < NT; nt++)
            #pragma unroll
            for (int h = 0; h < 2; h++) {
                int row = m0 + warpM * 32 + mt * 16 + g + h * 8;
                int col = n0 + warpN * 32 + nt * 8 + tg * 2;
                float v0 = fminf(fmaxf(acc[mt][nt][h * 2],     -10.f), 10.f);
                float v1 = fminf(fmaxf(acc[mt][nt][h * 2 + 1], -10.f), 10.f);
                ((u32*)g_qs)[((size_t)row * HIDDEN + col) >> 1] =
                    pack_h(__float2half_rn(v0), __float2half_rn(v1));
            }
}

// ---------------- fused MLP kernel (single-pass fp16 GEMM2/GEMM3) -----------
#define SP 100
#define SH 36
#define O_PF   0                           // 128*100 = 12800
#define O_B2   12800                       // 64*100  = 6400
#define O_HF   19200                       // 128*36  = 4608
#define O_B3   23808                       // 2 parities x 2304
#define SMEM_FUSED_U32 28416               // * 4 = 113664 B; x2 CTAs = 227328 <= 228KB

__global__ __launch_bounds__(256, 2) void mlp_fused(const float* __restrict__ coeffs,
                                                    const float* __restrict__ b2,
                                                    float* __restrict__ outf) {
    extern __shared__ u32 smem[];
    const u32 sbase = smem_u32(smem);
    const int tid = threadIdx.x, wid = tid >> 5, lane = tid & 31;
    const int g = lane >> 2, tg = lane & 3;
    const int r0 = blockIdx.x * 128;
    const int warpM = wid & 3, warpN = wid >> 2;   // warpN in {0,1}

    auto load_b2 = [&](int c) {
        u32 base = sbase + O_B2 * 4;
        #pragma unroll
        for (int i = 0; i < 6; i++) {
            int l = tid + i * 256;
            int n = l / 24, ch = l - n * 24;
            cpasync16(base + (u32)n * (SP * 4) + ch * 16,
                      g_w1t + (size_t)(c * 64 + n) * KP + ch * 8);
        }
    };
    auto load_b3 = [&](int c, int par) {
        u32 base = sbase + (u32)(O_B3 + par * 2304) * 4;
        #pragma unroll
        for (int i = 0; i < 2; i++) {
            int l = tid + i * 256;
            int n = l >> 3, ch = l & 7;
            cpasync16(base + (u32)n * (SH * 4) + ch * 16,
                      g_w2t + (size_t)n * MEMH + c * 64 + ch * 8);
        }
    };

    load_b2(0);
    load_b3(0, 0);
    asm volatile("cp.async.commit_group;");

    {
        const float c1 = coeffs[1], c2 = coeffs[2], c3 = coeffs[3];
        const u32* qb = (const u32*)g_qs + (size_t)r0 * (HD / 2);
        #pragma unroll
        for (int i = 0; i < 16; i++) {
            int l = tid + i * 256;
            int r = l >> 5, d2 = l & 31;
            u32 pv = qb[l];
            __half2 h2 = *(__half2*)&pv;
            float xa = __low2float(h2), xb = __high2float(h2);
            float xa2 = xa * xa, xb2 = xb * xb;
            float pa[3] = {c1 * xa, c2 * xa2, c3 * xa2 * xa};
            float pb[3] = {c1 * xb, c2 * xb2, c3 * xb2 * xb};
            #pragma unroll
            for (int fi = 0; fi < 3; fi++) {
                float a = fminf(fmaxf(pa[fi], -1e6f), 1e6f);
                float b = fminf(fmaxf(pb[fi], -1e6f), 1e6f);
                smem[O_PF + r * SP + fi * 32 + d2] =
                    pack_h(__float2half_rn(a), __float2half_rn(b));
            }
        }
    }
    asm volatile("cp.async.wait_group %0;" :: "n"(0));
    __syncthreads();

    float acc3[2][4][4];
    #pragma unroll
    for (int mt = 0; mt < 2; mt++)
        #pragma unroll
        for (int nt = 0; nt < 4; nt++)
            #pragma unroll
            for (int j = 0; j < 4; j++) acc3[mt][nt][j] = 0.f;

    for (int c = 0; c < 8; c++) {
        float acc2[2][4][4];
        #pragma unroll
        for (int mt = 0; mt < 2; mt++)
            #pragma unroll
            for (int nt = 0; nt < 4; nt++)
                #pragma unroll
                for (int j = 0; j < 4; j++) acc2[mt][nt][j] = 0.f;

        #pragma unroll
        for (int kt = 0; kt < 12; kt++) {
            u32 af[2][4];
            #pragma unroll
            for (int mt = 0; mt < 2; mt++) {
                int off = (warpM * 32 + mt * 16 + g) * SP + kt * 8 + tg;
                af[mt][0] = smem[O_PF + off];        af[mt][1] = smem[O_PF + off + 8 * SP];
                af[mt][2] = smem[O_PF + off + 4];    af[mt][3] = smem[O_PF + off + 8 * SP + 4];
            }
            u32 bv[4][2];
            #pragma unroll
            for (int nt = 0; nt < 4; nt++) {
                int off = (warpN * 32 + nt * 8 + g) * SP + kt * 8 + tg;
                bv[nt][0] = smem[O_B2 + off]; bv[nt][1] = smem[O_B2 + off + 4];
            }
            #pragma unroll
            for (int mt = 0; mt < 2; mt++)
                #pragma unroll
                for (int nt = 0; nt < 4; nt++) mma16816(acc2[mt][nt], af[mt], bv[nt]);
        }
        __syncthreads();

        #pragma unroll
        for (int mt = 0; mt < 2; mt++)
            #pragma unroll
            for (int nt = 0; nt < 4; nt++) {
                int colg = c * 64 + warpN * 32 + nt * 8 + tg * 2;
                float2 bb = *(const float2*)&g_b1eff[colg];
                #pragma unroll
                for (int h = 0; h < 2; h++) {
                    int row = warpM * 32 + mt * 16 + g + h * 8;
                    int cu  = warpN * 16 + nt * 4 + tg;
                    float v0 = fmaxf(acc2[mt][nt][h * 2]     + bb.x, 0.f);
                    float v1 = fmaxf(acc2[mt][nt][h * 2 + 1] + bb.y, 0.f);
                    smem[O_HF + row * SH + cu] =
                        pack_h(__float2half_rn(v0), __float2half_rn(v1));
                }
            }
        if (c < 7) {
            load_b2(c + 1);
            load_b3(c + 1, (c + 1) & 1);
            asm volatile("cp.async.commit_group;");
        }
        __syncthreads();

        const int b3o = O_B3 + (c & 1) * 2304;
        #pragma unroll
        for (int kt = 0; kt < 4; kt++) {
            u32 af[2][4];
            #pragma unroll
            for (int mt = 0; mt < 2; mt++) {
                int off = (warpM * 32 + mt * 16 + g) * SH + kt * 8 + tg;
                af[mt][0] = smem[O_HF + off];        af[mt][1] = smem[O_HF + off + 8 * SH];
                af[mt][2] = smem[O_HF + off + 4];    af[mt][3] = smem[O_HF + off + 8 * SH + 4];
            }
            u32 bv[4][2];
            #pragma unroll
            for (int nt = 0; nt < 4; nt++) {
                int off = (warpN * 32 + nt * 8 + g) * SH + kt * 8 + tg;
                bv[nt][0] = smem[b3o + off]; bv[nt][1] = smem[b3o + off + 4];
            }
            #pragma unroll
            for (int mt = 0; mt < 2; mt++)
                #pragma unroll
                for (int nt = 0; nt < 4; nt++) mma16816(acc3[mt][nt], af[mt], bv[nt]);
        }
        if (c < 7) {
            asm volatile("cp.async.wait_group %0;" :: "n"(0));
            __syncthreads();
        }
    }

    #pragma unroll
    for (int mt = 0; mt < 2; mt++)
        #pragma unroll
        for (int nt = 0; nt < 4; nt++) {
            int col = warpN * 32 + nt * 8 + tg * 2;
            float2 bb = *(const float2*)&b2[col];
            #pragma unroll
            for (int h = 0; h < 2; h++) {
                int row = r0 + warpM * 32 + mt * 16 + g + h * 8;
                float2 o = make_float2(acc3[mt][nt][h * 2] + bb.x,
                                       acc3[mt][nt][h * 2 + 1] + bb.y);
                *(float2*)&outf[(size_t)row * HD + col] = o;
            }
        }
}

// ---------------------------------------------------------------------------
extern "C" void kernel_launch(void* const* d_in, const int* in_sizes, int n_in,
                              void* d_out, int out_size) {
    const float* hs     = (const float*)d_in[0];
    const float* Wq     = (const float*)d_in[1];
    const float* coeffs = (const float*)d_in[2];
    const float* W1     = (const float*)d_in[3];
    const float* b1     = (const float*)d_in[4];
    const float* W2     = (const float*)d_in[5];
    const float* b2     = (const float*)d_in[6];
    float* out = (float*)d_out;

    prep_all<<<NB_ALL, 256>>>(hs, Wq);

    constexpr int SM1 = 3840 * 4 * 2;                            // 30720 B
    constexpr int SMF = SMEM_FUSED_U32 * 4;                      // 113664 B
    cudaFuncSetAttribute(gemm1_kernel, cudaFuncAttributeMaxDynamicSharedMemorySize, SM1);
    cudaFuncSetAttribute(mlp_fused,    cudaFuncAttributeMaxDynamicSharedMemorySize, SMF);

    gemm1_kernel<<<dim3(TOKENS / 128, 13), 256, SM1>>>(W1, W2, b1, coeffs);
    mlp_fused<<<FLATR / 128, 256, SMF>>>(coeffs, b2, out);
}

// round 17
// speedup vs baseline: 1.0414x; 1.0414x over previous
#include <cuda_runtime.h>
#include <cuda_bf16.h>
#include <cuda_fp16.h>

// ---------------------------------------------------------------------------
// AtlasAttention, legacy mma.sync fp16 single-pass, fused MLP. (R15 champion
// + __launch_bounds__(256,2) on gemm1 to guarantee 2 CTAs/SM latency hiding.)
//   prep:  hs -> fp16 scratch; Wq^T coalesced 64x64 tile transpose
//   GEMM1: q = clip(hs@Wq) -> g_qs fp16  (y==6 slice: W1T/W2T/b1eff prep)
//   GEMM2: h = relu(P@W1eff + b1eff)   GEMM3: out = H@W2[:, :64] + b2
//   Exact folds: b1eff (const poly block), W2[:, :64] slice.
// ---------------------------------------------------------------------------

typedef unsigned int u32;

#define TOKENS 8192
#define HIDDEN 768
#define FLATR  98304
#define MEMH   512
#define KP     192
#define HD     64

__device__ __align__(16) __half g_hs_f[TOKENS * HIDDEN];
__device__ __align__(16) __half g_wqt[HIDDEN * HIDDEN];   // [n][k] fp16
__device__ __align__(16) __half g_w1t[MEMH * KP];         // [n=512][k=192]
__device__ __align__(16) __half g_w2t[HD * MEMH];         // [n=64][k=512]
__device__ __align__(16) __half g_qs[(size_t)TOKENS * HIDDEN];  // clipped q, fp16
__device__ float g_b1eff[MEMH];

// ---------------- helpers ----------------
__device__ __forceinline__ u32 smem_u32(const void* p) {
    u32 a; asm("{ .reg .u64 t; cvta.to.shared.u64 t, %1; cvt.u32.u64 %0, t; }"
               : "=r"(a) : "l"(p)); return a;
}
__device__ __forceinline__ u32 pack_h(__half a, __half b) {
    return (u32)__half_as_ushort(a) | ((u32)__half_as_ushort(b) << 16);
}
__device__ __forceinline__ void mma16816(float* c, const u32* a, const u32* b) {
    asm volatile(
        "mma.sync.aligned.m16n8k16.row.col.f32.f16.f16.f32 "
        "{%0,%1,%2,%3}, {%4,%5,%6,%7}, {%8,%9}, {%0,%1,%2,%3};"
        : "+f"(c[0]), "+f"(c[1]), "+f"(c[2]), "+f"(c[3])
        : "r"(a[0]), "r"(a[1]), "r"(a[2]), "r"(a[3]), "r"(b[0]), "r"(b[1]));
}
__device__ __forceinline__ void cpasync16(u32 dst, const void* src) {
    asm volatile("cp.async.cg.shared.global [%0], [%1], 16;" :: "r"(dst), "l"(src));
}

// ---------------- prep kernel: hs->fp16 + Wq^T only ----------------
#define NB_HS   1536
#define NB_WQT  144
#define NB_ALL  (NB_HS + NB_WQT)

__global__ void prep_all(const float* __restrict__ hs, const float* __restrict__ Wq) {
    const int b = blockIdx.x, tid = threadIdx.x;
    if (b < NB_HS) {
        #pragma unroll
        for (int j = 0; j < 4; j++) {
            int i4 = (b * 256 + tid) + j * (NB_HS * 256);
            float4 v = ((const float4*)hs)[i4];
            u32 f0 = pack_h(__float2half_rn(v.x), __float2half_rn(v.y));
            u32 f1 = pack_h(__float2half_rn(v.z), __float2half_rn(v.w));
            ((uint2*)g_hs_f)[i4] = make_uint2(f0, f1);
        }
    } else {
        __shared__ float ts[64][65];
        int t = b - NB_HS;
        int kb = (t / 12) * 64, nb = (t % 12) * 64;
        int tx = tid & 63, ty = tid >> 6;
        #pragma unroll
        for (int i = 0; i < 16; i++) {
            int row = ty + i * 4;
            ts[row][tx] = Wq[(size_t)(kb + row) * HIDDEN + nb + tx];
        }
        __syncthreads();
        #pragma unroll
        for (int i = 0; i < 16; i++) {
            int n = ty + i * 4;
            g_wqt[(size_t)(nb + n) * HIDDEN + kb + tx] = __float2half_rn(ts[tx][n]);
        }
    }
}

// ---------------- GEMM1 (BN=128) + embedded MLP-weight prep -----------------
// grid (64, 7): y<6 -> GEMM tile; y==6 -> prep items:
//   [0,96): W1T 32x32 tiles; [96,128): W2T 32x32 tiles; [128,130): b1eff
__global__ __launch_bounds__(256, 2) void gemm1_kernel(const float* __restrict__ W1,
                                                       const float* __restrict__ W2,
                                                       const float* __restrict__ b1,
                                                       const float* __restrict__ coeffs) {
    constexpr int BM = 128, BN = 128, BK = 32, NT = 8;
    constexpr int SA = 20;
    constexpr int TILE_A = BM * SA, TILE_B = BN * SA;
    constexpr int STAGE = TILE_A + TILE_B;
    constexpr int K = HIDDEN, NIT = K / BK;

    extern __shared__ u32 smem[];
    const int tid = threadIdx.x;

    if (blockIdx.y == 6) {
        float* ts = (float*)smem;                    // [32][33]
        const int tx = tid & 31, ty = tid >> 5;
        for (int item = blockIdx.x; item < 130; item += 64) {
            if (item < 96) {
                int kb = (item / 16) * 32, nb = (item % 16) * 32;
                #pragma unroll
                for (int i = 0; i < 4; i++) {
                    int kr = ty + i * 8;
                    ts[kr * 33 + tx] = W1[(size_t)(HD + kb + kr) * MEMH + nb + tx];
                }
                __syncthreads();
                #pragma unroll
                for (int i = 0; i < 4; i++) {
                    int n = ty + i * 8;
                    g_w1t[(size_t)(nb + n) * KP + kb + tx] = __float2half_rn(ts[tx * 33 + n]);
                }
                __syncthreads();
            } else if (item < 128) {
                int t = item - 96;
                int kb = (t / 2) * 32, nb = (t % 2) * 32;
                #pragma unroll
                for (int i = 0; i < 4; i++) {
                    int kr = ty + i * 8;
                    ts[kr * 33 + tx] = W2[(size_t)(kb + kr) * 256 + nb + tx];
                }
                __syncthreads();
                #pragma unroll
                for (int i = 0; i < 4; i++) {
                    int n = ty + i * 8;
                    g_w2t[(size_t)(nb + n) * MEMH + kb + tx] = __float2half_rn(ts[tx * 33 + n]);
                }
                __syncthreads();
            } else {
                int n = (item - 128) * 256 + tid;
                float s = 0.f;
                #pragma unroll 8
                for (int j = 0; j < HD; j++) s += W1[j * MEMH + n];
                g_b1eff[n] = b1[n] + coeffs[0] * s;
            }
        }
        return;
    }

    const u32 sbase = smem_u32(smem);
    const int wid = tid >> 5, lane = tid & 31;
    const int g = lane >> 2, tg = lane & 3;
    const int m0 = blockIdx.x * BM, n0 = blockIdx.y * BN;
    const int warpM = wid & 3, warpN = wid >> 2;

    float acc[2][NT][4];
    #pragma unroll
    for (int mt = 0; mt < 2; mt++)
        #pragma unroll
        for (int nt = 0; nt < NT; nt++)
            #pragma unroll
            for (int j = 0; j < 4; j++) acc[mt][nt][j] = 0.f;

    auto load_stage = [&](int s, int k0) {
        const u32 stb = sbase + (u32)s * STAGE * 4;
        #pragma unroll
        for (int idx = 0; idx < 2; idx++) {
            int l = tid + idx * 256;
            int r = l >> 2, c = l & 3;
            cpasync16(stb + (u32)(r * SA) * 4 + c * 16,
                      g_hs_f + (size_t)(m0 + r) * K + k0 + c * 8);
        }
        #pragma unroll
        for (int idx = 0; idx < 2; idx++) {
            int l = tid + idx * 256;
            int r = l >> 2, c = l & 3;
            cpasync16(stb + (u32)(TILE_A + r * SA) * 4 + c * 16,
                      g_wqt + (size_t)(n0 + r) * K + k0 + c * 8);
        }
        asm volatile("cp.async.commit_group;");
    };

    load_stage(0, 0);
    for (int it = 0; it < NIT; it++) {
        if (it + 1 < NIT) {
            load_stage((it + 1) & 1, (it + 1) * BK);
            asm volatile("cp.async.wait_group %0;" :: "n"(1));
        } else {
            asm volatile("cp.async.wait_group %0;" :: "n"(0));
        }
        __syncthreads();
        const u32* S = smem + (it & 1) * STAGE;
        #pragma unroll
        for (int kt = 0; kt < 2; kt++) {
            u32 af[2][4];
            #pragma unroll
            for (int mt = 0; mt < 2; mt++) {
                int off = (warpM * 32 + mt * 16 + g) * SA + kt * 8 + tg;
                af[mt][0] = S[off];       af[mt][1] = S[off + 8 * SA];
                af[mt][2] = S[off + 4];   af[mt][3] = S[off + 8 * SA + 4];
            }
            u32 bv[NT][2];
            #pragma unroll
            for (int nt = 0; nt < NT; nt++) {
                int off = (warpN * NT * 8 + nt * 8 + g) * SA + kt * 8 + tg;
                const u32* SB = S + TILE_A;
                bv[nt][0] = SB[off]; bv[nt][1] = SB[off + 4];
            }
            #pragma unroll
            for (int mt = 0; mt < 2; mt++)
                #pragma unroll
                for (int nt = 0; nt < NT; nt++) mma16816(acc[mt][nt], af[mt], bv[nt]);
        }
        __syncthreads();
    }

    #pragma unroll
    for (int mt = 0; mt < 2; mt++)
        #pragma unroll
        for (int nt = 0; nt < NT; nt++)
            #pragma unroll
            for (int h = 0; h < 2; h++) {
                int row = m0 + warpM * 32 + mt * 16 + g + h * 8;
                int col = n0 + warpN * NT * 8 + nt * 8 + tg * 2;
                float v0 = fminf(fmaxf(acc[mt][nt][h * 2],     -10.f), 10.f);
                float v1 = fminf(fmaxf(acc[mt][nt][h * 2 + 1], -10.f), 10.f);
                ((u32*)g_qs)[((size_t)row * HIDDEN + col) >> 1] =
                    pack_h(__float2half_rn(v0), __float2half_rn(v1));
            }
}

// ---------------- fused MLP kernel (single-pass fp16 GEMM2/GEMM3) -----------
#define SP 100
#define SH 36
#define O_PF   0                           // 128*100 = 12800
#define O_B2   12800                       // 64*100  = 6400
#define O_HF   19200                       // 128*36  = 4608
#define O_B3   23808                       // 2 parities x 2304
#define SMEM_FUSED_U32 28416               // * 4 = 113664 B; x2 CTAs = 227328 <= 228KB

__global__ __launch_bounds__(256, 2) void mlp_fused(const float* __restrict__ coeffs,
                                                    const float* __restrict__ b2,
                                                    float* __restrict__ outf) {
    extern __shared__ u32 smem[];
    const u32 sbase = smem_u32(smem);
    const int tid = threadIdx.x, wid = tid >> 5, lane = tid & 31;
    const int g = lane >> 2, tg = lane & 3;
    const int r0 = blockIdx.x * 128;
    const int warpM = wid & 3, warpN = wid >> 2;   // warpN in {0,1}

    auto load_b2 = [&](int c) {
        u32 base = sbase + O_B2 * 4;
        #pragma unroll
        for (int i = 0; i < 6; i++) {
            int l = tid + i * 256;
            int n = l / 24, ch = l - n * 24;
            cpasync16(base + (u32)n * (SP * 4) + ch * 16,
                      g_w1t + (size_t)(c * 64 + n) * KP + ch * 8);
        }
    };
    auto load_b3 = [&](int c, int par) {
        u32 base = sbase + (u32)(O_B3 + par * 2304) * 4;
        #pragma unroll
        for (int i = 0; i < 2; i++) {
            int l = tid + i * 256;
            int n = l >> 3, ch = l & 7;
            cpasync16(base + (u32)n * (SH * 4) + ch * 16,
                      g_w2t + (size_t)n * MEMH + c * 64 + ch * 8);
        }
    };

    load_b2(0);
    load_b3(0, 0);
    asm volatile("cp.async.commit_group;");

    {
        const float c1 = coeffs[1], c2 = coeffs[2], c3 = coeffs[3];
        const u32* qb = (const u32*)g_qs + (size_t)r0 * (HD / 2);
        #pragma unroll
        for (int i = 0; i < 16; i++) {
            int l = tid + i * 256;
            int r = l >> 5, d2 = l & 31;
            u32 pv = qb[l];
            __half2 h2 = *(__half2*)&pv;
            float xa = __low2float(h2), xb = __high2float(h2);
            float xa2 = xa * xa, xb2 = xb * xb;
            float pa[3] = {c1 * xa, c2 * xa2, c3 * xa2 * xa};
            float pb[3] = {c1 * xb, c2 * xb2, c3 * xb2 * xb};
            #pragma unroll
            for (int fi = 0; fi < 3; fi++) {
                float a = fminf(fmaxf(pa[fi], -1e6f), 1e6f);
                float b = fminf(fmaxf(pb[fi], -1e6f), 1e6f);
                smem[O_PF + r * SP + fi * 32 + d2] =
                    pack_h(__float2half_rn(a), __float2half_rn(b));
            }
        }
    }
    asm volatile("cp.async.wait_group %0;" :: "n"(0));
    __syncthreads();

    float acc3[2][4][4];
    #pragma unroll
    for (int mt = 0; mt < 2; mt++)
        #pragma unroll
        for (int nt = 0; nt < 4; nt++)
            #pragma unroll
            for (int j = 0; j < 4; j++) acc3[mt][nt][j] = 0.f;

    for (int c = 0; c < 8; c++) {
        float acc2[2][4][4];
        #pragma unroll
        for (int mt = 0; mt < 2; mt++)
            #pragma unroll
            for (int nt = 0; nt < 4; nt++)
                #pragma unroll
                for (int j = 0; j < 4; j++) acc2[mt][nt][j] = 0.f;

        #pragma unroll
        for (int kt = 0; kt < 12; kt++) {
            u32 af[2][4];
            #pragma unroll
            for (int mt = 0; mt < 2; mt++) {
                int off = (warpM * 32 + mt * 16 + g) * SP + kt * 8 + tg;
                af[mt][0] = smem[O_PF + off];        af[mt][1] = smem[O_PF + off + 8 * SP];
                af[mt][2] = smem[O_PF + off + 4];    af[mt][3] = smem[O_PF + off + 8 * SP + 4];
            }
            u32 bv[4][2];
            #pragma unroll
            for (int nt = 0; nt < 4; nt++) {
                int off = (warpN * 32 + nt * 8 + g) * SP + kt * 8 + tg;
                bv[nt][0] = smem[O_B2 + off]; bv[nt][1] = smem[O_B2 + off + 4];
            }
            #pragma unroll
            for (int mt = 0; mt < 2; mt++)
                #pragma unroll
                for (int nt = 0; nt < 4; nt++) mma16816(acc2[mt][nt], af[mt], bv[nt]);
        }
        __syncthreads();

        #pragma unroll
        for (int mt = 0; mt < 2; mt++)
            #pragma unroll
            for (int nt = 0; nt < 4; nt++) {
                int colg = c * 64 + warpN * 32 + nt * 8 + tg * 2;
                float2 bb = *(const float2*)&g_b1eff[colg];
                #pragma unroll
                for (int h = 0; h < 2; h++) {
                    int row = warpM * 32 + mt * 16 + g + h * 8;
                    int cu  = warpN * 16 + nt * 4 + tg;
                    float v0 = fmaxf(acc2[mt][nt][h * 2]     + bb.x, 0.f);
                    float v1 = fmaxf(acc2[mt][nt][h * 2 + 1] + bb.y, 0.f);
                    smem[O_HF + row * SH + cu] =
                        pack_h(__float2half_rn(v0), __float2half_rn(v1));
                }
            }
        if (c < 7) {
            load_b2(c + 1);
            load_b3(c + 1, (c + 1) & 1);
            asm volatile("cp.async.commit_group;");
        }
        __syncthreads();

        const int b3o = O_B3 + (c & 1) * 2304;
        #pragma unroll
        for (int kt = 0; kt < 4; kt++) {
            u32 af[2][4];
            #pragma unroll
            for (int mt = 0; mt < 2; mt++) {
                int off = (warpM * 32 + mt * 16 + g) * SH + kt * 8 + tg;
                af[mt][0] = smem[O_HF + off];        af[mt][1] = smem[O_HF + off + 8 * SH];
                af[mt][2] = smem[O_HF + off + 4];    af[mt][3] = smem[O_HF + off + 8 * SH + 4];
            }
            u32 bv[4][2];
            #pragma unroll
            for (int nt = 0; nt < 4; nt++) {
                int off = (warpN * 32 + nt * 8 + g) * SH + kt * 8 + tg;
                bv[nt][0] = smem[b3o + off]; bv[nt][1] = smem[b3o + off + 4];
            }
            #pragma unroll
            for (int mt = 0; mt < 2; mt++)
                #pragma unroll
                for (int nt = 0; nt < 4; nt++) mma16816(acc3[mt][nt], af[mt], bv[nt]);
        }
        if (c < 7) {
            asm volatile("cp.async.wait_group %0;" :: "n"(0));
            __syncthreads();
        }
    }

    #pragma unroll
    for (int mt = 0; mt < 2; mt++)
        #pragma unroll
        for (int nt = 0; nt < 4; nt++) {
            int col = warpN * 32 + nt * 8 + tg * 2;
            float2 bb = *(const float2*)&b2[col];
            #pragma unroll
            for (int h = 0; h < 2; h++) {
                int row = r0 + warpM * 32 + mt * 16 + g + h * 8;
                float2 o = make_float2(acc3[mt][nt][h * 2] + bb.x,
                                       acc3[mt][nt][h * 2 + 1] + bb.y);
                *(float2*)&outf[(size_t)row * HD + col] = o;
            }
        }
}

// ---------------------------------------------------------------------------
extern "C" void kernel_launch(void* const* d_in, const int* in_sizes, int n_in,
                              void* d_out, int out_size) {
    const float* hs     = (const float*)d_in[0];
    const float* Wq     = (const float*)d_in[1];
    const float* coeffs = (const float*)d_in[2];
    const float* W1     = (const float*)d_in[3];
    const float* b1     = (const float*)d_in[4];
    const float* W2     = (const float*)d_in[5];
    const float* b2     = (const float*)d_in[6];
    float* out = (float*)d_out;

    prep_all<<<NB_ALL, 256>>>(hs, Wq);

    constexpr int SM1 = (128 * 20 + 128 * 20) * 4 * 2;           // 40960 B
    constexpr int SMF = SMEM_FUSED_U32 * 4;                      // 113664 B
    cudaFuncSetAttribute(gemm1_kernel, cudaFuncAttributeMaxDynamicSharedMemorySize, SM1);
    cudaFuncSetAttribute(mlp_fused,    cudaFuncAttributeMaxDynamicSharedMemorySize, SMF);

    gemm1_kernel<<<dim3(TOKENS / 128, 7), 256, SM1>>>(W1, W2, b1, coeffs);
    mlp_fused<<<FLATR / 128, 256, SMF>>>(coeffs, b2, out);
}